// round 6
// baseline (speedup 1.0000x reference)
#include <cuda_runtime.h>
#include <math.h>
#include <cstdint>

#define BB 32
#define EE 512
#define HH 1024
#define G4 4096
#define LL 64
#define VV 32000

typedef unsigned long long u64;

// ---------------- device scratch ----------------
__device__ __align__(16) float  g_h[BB*HH];
__device__ __align__(16) float  g_c[BB*HH];
__device__ __align__(16) float  g_enc[LL*BB*HH];     // [l][b][d]
__device__ __align__(16) float2 g_h2[HH*BB];         // [k][b] dup pairs
__device__ __align__(16) float2 g_e2[HH*BB];         // dup pairs
__device__ __align__(16) float2 g_ctx2[HH*BB];       // dup pairs
__device__ __align__(16) float2 g_inp2[HH*BB];       // dup pairs
__device__ __align__(16) float2 g_xemb2[EE*BB];      // dup pairs
__device__ __align__(16) float  g_part[4*BB*G4];     // gate partials
__device__ __align__(16) float  g_part2[16*BB*HH];   // comb partials
__device__ int g_tok[BB];
__device__ u64 g_slot[BB];

// ---------------- helpers ----------------
__device__ __forceinline__ void fma2(u64 &d, u64 a, u64 b){
    asm("fma.rn.f32x2 %0, %1, %2, %0;" : "+l"(d) : "l"(a), "l"(b));
}
__device__ __forceinline__ u64 pk(float x, float y){
    u64 r; asm("mov.b64 %0,{%1,%2};" : "=l"(r) : "f"(x), "f"(y)); return r;
}
__device__ __forceinline__ float2 up(u64 v){
    float2 r; asm("mov.b64 {%0,%1},%2;" : "=f"(r.x), "=f"(r.y) : "l"(v)); return r;
}
__device__ __forceinline__ float sigf(float x){ return 1.0f/(1.0f + expf(-x)); }

__device__ __forceinline__ unsigned ordf(float f){
    unsigned u = __float_as_uint(f);
    return (u & 0x80000000u) ? ~u : (u | 0x80000000u);
}
__device__ __forceinline__ float unordf(unsigned u){
    return __uint_as_float((u & 0x80000000u) ? (u ^ 0x80000000u) : ~u);
}

__device__ __forceinline__ void cpa16(void* s, const void* g){
    uint32_t sa = (uint32_t)__cvta_generic_to_shared(s);
    asm volatile("cp.async.cg.shared.global [%0], [%1], 16;" :: "r"(sa), "l"(g));
}
#define CP_COMMIT asm volatile("cp.async.commit_group;" ::: "memory")
#define CP_WAIT(n) asm volatile("cp.async.wait_group %0;" :: "n"(n) : "memory")

// ---------------- init (phase 0: encoder, gathers emb t=0; phase 1: decoder) ----------------
__global__ __launch_bounds__(256) void init_state(
    const int* __restrict__ x, const float* __restrict__ emb, int phase)
{
    int i = blockIdx.x*256 + threadIdx.x;   // 32768 threads
    if (i < BB*HH){ g_h[i]=0.0f; g_c[i]=0.0f; g_h2[i]=make_float2(0.f,0.f); }
    if (i < BB){ g_tok[i]=127; g_slot[i]=0ULL; }
    if (phase==0 && i < EE*BB){
        int k=i>>5, b=i&31;
        float v = emb[(size_t)x[b*LL]*EE + k];
        g_xemb2[i] = make_float2(v,v);
    }
}

// =====================================================================
// Unified split-K 2-segment GEMM. A buffers: [k][32] duplicated pairs.
// W: [K][ldw] row-major. 16-row tiles. 4-stage cp.async ring.
// grid (ldw/128, nslices), 256 threads. Block: 32 b x 128 cols.
// =====================================================================
__device__ __forceinline__ void seg_resolve(
    int g, int k1u, const float* A1, const float* W1,
    const float* A2, const float* W2, int ldw,
    const float*& At, const float*& Wp)
{
    if (g < k1u){ At = A1 + g*1024; Wp = W1 + (size_t)g*16*ldw; }
    else { int h = g-k1u; At = A2 + h*1024; Wp = W2 + (size_t)h*16*ldw; }
}

__device__ __forceinline__ void load_tile(
    int buf, int tid, const float* At, const float* Wp, int ldw, int colbase,
    float (*sW)[16*128], float (*sA)[16*64])
{
    for (int i=tid;i<512;i+=256){
        int row=i>>5, col=(i&31)*4;
        cpa16(&sW[buf][row*128+col], Wp + (size_t)row*ldw + colbase + col);
    }
    cpa16(&sA[buf][tid*4], At + tid*4);
    CP_COMMIT;
}

__device__ __forceinline__ void mma_tile(
    const float* pw, const float* pa, int vl, int tb8,
    u64&A00,u64&A01,u64&A10,u64&A11,u64&A20,u64&A21,u64&A30,u64&A31)
{
    #pragma unroll
    for (int kk=0;kk<16;kk++){
        float4 w = *(const float4*)(pw + kk*128 + vl);
        const u64* wp = (const u64*)&w;
        float4 a01 = *(const float4*)(pa + kk*64 + tb8);
        float4 a23 = *(const float4*)(pa + kk*64 + tb8 + 4);
        const u64* s01 = (const u64*)&a01;
        const u64* s23 = (const u64*)&a23;
        fma2(A00,s01[0],wp[0]); fma2(A01,s01[0],wp[1]);
        fma2(A10,s01[1],wp[0]); fma2(A11,s01[1],wp[1]);
        fma2(A20,s23[0],wp[0]); fma2(A21,s23[0],wp[1]);
        fma2(A30,s23[1],wp[0]); fma2(A31,s23[1],wp[1]);
    }
}

__global__ __launch_bounds__(256) void gemm_seg(
    const float* __restrict__ A1, const float* __restrict__ W1, int k1u,
    const float* __restrict__ A2, const float* __restrict__ W2,
    int ldw, int tpu, float* __restrict__ parts)
{
    __shared__ float sW[4][16*128];
    __shared__ float sA[4][16*64];
    int tid = threadIdx.x;
    int colbase = blockIdx.x*128;
    int slice = blockIdx.y;
    int u0 = slice*tpu;
    int tb = tid>>5, tv = tid&31;
    int b0 = tb*4, n4 = tv*4, tb8 = tb*8;

    #pragma unroll
    for (int p=0;p<3;p++){
        const float *At,*Wp;
        seg_resolve(u0+p, k1u, A1,W1,A2,W2,ldw, At,Wp);
        load_tile(p, tid, At, Wp, ldw, colbase, sW, sA);
    }

    u64 A00=0,A01=0,A10=0,A11=0,A20=0,A21=0,A30=0,A31=0;

    for (int u=0; u<tpu; u++){
        int rem = tpu-1-u;
        if (rem >= 2) CP_WAIT(2);
        else if (rem == 1) CP_WAIT(1);
        else CP_WAIT(0);
        __syncthreads();
        if (u+3 < tpu){
            const float *At,*Wp;
            seg_resolve(u0+u+3, k1u, A1,W1,A2,W2,ldw, At,Wp);
            load_tile((u+3)&3, tid, At, Wp, ldw, colbase, sW, sA);
        }
        mma_tile(sW[u&3], sA[u&3], n4, tb8, A00,A01,A10,A11,A20,A21,A30,A31);
    }
    float2 r0a=up(A00), r0b=up(A01);
    float2 r1a=up(A10), r1b=up(A11);
    float2 r2a=up(A20), r2b=up(A21);
    float2 r3a=up(A30), r3b=up(A31);
    float* pp = parts + (size_t)slice*BB*ldw + colbase + n4;
    *(float4*)(pp + (size_t)(b0+0)*ldw) = make_float4(r0a.x,r0a.y,r0b.x,r0b.y);
    *(float4*)(pp + (size_t)(b0+1)*ldw) = make_float4(r1a.x,r1a.y,r1b.x,r1b.y);
    *(float4*)(pp + (size_t)(b0+2)*ldw) = make_float4(r2a.x,r2a.y,r2b.x,r2b.y);
    *(float4*)(pp + (size_t)(b0+3)*ldw) = make_float4(r3a.x,r3a.y,r3b.x,r3b.y);
}

// =====================================================================
// Combine 4 gate-partial slices + LSTM cell (i,f,g,o). 4 cells/thread.
// Enc: stores enc row + gathers next-step embedding. Dec: resets slots.
// grid 32 x 256.
// =====================================================================
__global__ __launch_bounds__(256) void lstm_update(
    const float* __restrict__ bias, int isEnc, int t,
    const int* __restrict__ x, const float* __restrict__ emb)
{
    int gtid = blockIdx.x*256 + threadIdx.x;     // 8192
    int b = gtid>>8, d = (gtid&255)*4;

    float4 gi = *(const float4*)&bias[d];
    float4 gf = *(const float4*)&bias[HH+d];
    float4 gg = *(const float4*)&bias[2*HH+d];
    float4 go = *(const float4*)&bias[3*HH+d];
    #pragma unroll
    for (int s=0;s<4;s++){
        const float* p = g_part + (size_t)(s*BB+b)*G4;
        float4 a = *(const float4*)&p[d];
        float4 bq = *(const float4*)&p[HH+d];
        float4 cq = *(const float4*)&p[2*HH+d];
        float4 dq = *(const float4*)&p[3*HH+d];
        gi.x+=a.x; gi.y+=a.y; gi.z+=a.z; gi.w+=a.w;
        gf.x+=bq.x; gf.y+=bq.y; gf.z+=bq.z; gf.w+=bq.w;
        gg.x+=cq.x; gg.y+=cq.y; gg.z+=cq.z; gg.w+=cq.w;
        go.x+=dq.x; go.y+=dq.y; go.z+=dq.z; go.w+=dq.w;
    }
    float4 c4 = *(const float4*)&g_c[b*HH+d];
    float ci[4]={c4.x,c4.y,c4.z,c4.w};
    float gia[4]={gi.x,gi.y,gi.z,gi.w}, gfa[4]={gf.x,gf.y,gf.z,gf.w};
    float gga[4]={gg.x,gg.y,gg.z,gg.w}, goa[4]={go.x,go.y,go.z,go.w};
    float hv[4];
    #pragma unroll
    for (int i=0;i<4;i++){
        float c = sigf(gfa[i])*ci[i] + sigf(gia[i])*tanhf(gga[i]);
        hv[i] = sigf(goa[i])*tanhf(c);
        ci[i] = c;
    }
    *(float4*)&g_c[b*HH+d] = make_float4(ci[0],ci[1],ci[2],ci[3]);
    *(float4*)&g_h[b*HH+d] = make_float4(hv[0],hv[1],hv[2],hv[3]);
    #pragma unroll
    for (int i=0;i<4;i++) g_h2[(d+i)*BB+b] = make_float2(hv[i],hv[i]);

    if (isEnc){
        *(float4*)&g_enc[((size_t)t*BB+b)*HH+d] = make_float4(hv[0],hv[1],hv[2],hv[3]);
        if (t+1 < LL){
            for (int i=gtid;i<EE*BB;i+=8192){
                int k=i>>5, bb=i&31;
                float v = emb[(size_t)x[bb*LL+t+1]*EE + k];
                g_xemb2[i] = make_float2(v,v);
            }
        }
    } else {
        if (blockIdx.x==0 && threadIdx.x<BB) g_slot[threadIdx.x]=0ULL;
    }
}

// =====================================================================
// Attention: e=dec_embed[tok]; softmax([e,h]@attn_w+b); ctx. Writes e2, ctx2.
// =====================================================================
__global__ __launch_bounds__(256) void attn_ctx(
    const float* __restrict__ demb, const float* __restrict__ aw,
    const float* __restrict__ ab)
{
    int b = blockIdx.x, tid = threadIdx.x;
    __shared__ float sE[HH], sH2[HH], sPP[4][64], sS[64];
    int tok = g_tok[b];
    for (int k=tid; k<HH; k+=256){
        float e = demb[(size_t)tok*HH + k];
        sE[k]=e; g_e2[k*BB+b]=make_float2(e,e);
        sH2[k]=g_h[b*HH+k];
    }
    __syncthreads();

    {   // scores: 4-way K split over 512-row chunks of attn_w
        int l = tid & 63, q = tid >> 6;
        const float* src = (q<2) ? (sE + q*512) : (sH2 + (q-2)*512);
        const float* wb  = aw + (size_t)q*512*64;
        float a0=0.f,a1=0.f,a2=0.f,a3=0.f,a4=0.f,a5=0.f,a6=0.f,a7=0.f;
        #pragma unroll 2
        for (int k=0;k<512;k+=8){
            a0 += src[k+0]*wb[(k+0)*64 + l];
            a1 += src[k+1]*wb[(k+1)*64 + l];
            a2 += src[k+2]*wb[(k+2)*64 + l];
            a3 += src[k+3]*wb[(k+3)*64 + l];
            a4 += src[k+4]*wb[(k+4)*64 + l];
            a5 += src[k+5]*wb[(k+5)*64 + l];
            a6 += src[k+6]*wb[(k+6)*64 + l];
            a7 += src[k+7]*wb[(k+7)*64 + l];
        }
        sPP[q][l] = ((a0+a1)+(a2+a3))+((a4+a5)+(a6+a7));
    }
    __syncthreads();
    if (tid == 0){
        float sv[64]; float m = -INFINITY;
        for (int i=0;i<64;i++){
            float v = sPP[0][i]+sPP[1][i]+sPP[2][i]+sPP[3][i]+ab[i];
            sv[i]=v; m = fmaxf(m,v);
        }
        float sum = 0.0f;
        for (int i=0;i<64;i++){ float e = expf(sv[i]-m); sS[i]=e; sum += e; }
        float inv = 1.0f/sum;
        for (int i=0;i<64;i++) sS[i] *= inv;
    }
    __syncthreads();
    {   // ctx: 4 contiguous d per thread; write dup pairs
        int d = tid*4;
        float ax=0.f, ay=0.f, az=0.f, awc=0.f;
        #pragma unroll 8
        for (int l=0;l<64;l++){
            float s = sS[l];
            float4 ev = *(const float4*)&g_enc[((size_t)l*BB + b)*HH + d];
            ax += s*ev.x; ay += s*ev.y; az += s*ev.z; awc += s*ev.w;
        }
        g_ctx2[(d+0)*BB+b]=make_float2(ax,ax);
        g_ctx2[(d+1)*BB+b]=make_float2(ay,ay);
        g_ctx2[(d+2)*BB+b]=make_float2(az,az);
        g_ctx2[(d+3)*BB+b]=make_float2(awc,awc);
    }
}

// =====================================================================
// comb partial reduce (16 slices) + bias + relu -> inp2 (dup pairs)
// grid 32 x 256, 4 elems/thread
// =====================================================================
__global__ __launch_bounds__(256) void comb_fin(const float* __restrict__ cb)
{
    int gtid = blockIdx.x*256 + threadIdx.x;  // 8192
    int b = gtid>>8, d = (gtid&255)*4;
    float4 v = *(const float4*)&cb[d];
    #pragma unroll
    for (int s=0;s<16;s++){
        float4 a = *(const float4*)&g_part2[(size_t)(s*BB+b)*HH + d];
        v.x+=a.x; v.y+=a.y; v.z+=a.z; v.w+=a.w;
    }
    float r0=fmaxf(v.x,0.f), r1=fmaxf(v.y,0.f), r2=fmaxf(v.z,0.f), r3=fmaxf(v.w,0.f);
    g_inp2[(d+0)*BB+b]=make_float2(r0,r0);
    g_inp2[(d+1)*BB+b]=make_float2(r1,r1);
    g_inp2[(d+2)*BB+b]=make_float2(r2,r2);
    g_inp2[(d+3)*BB+b]=make_float2(r3,r3);
}

// =====================================================================
// Output projection + fused per-batch argmax. 4-stage cp.async ring.
// grid 250 x 256.
// =====================================================================
__global__ __launch_bounds__(256) void out_proj(
    const float* __restrict__ W, const float* __restrict__ ob,
    float* __restrict__ out, int t)
{
    __shared__ float sW[4][16*128];
    __shared__ float sA[4][16*64];
    int tid = threadIdx.x;
    int v0 = blockIdx.x*128;
    int tb = tid>>5, tv = tid&31;
    int b0 = tb*4, vl = tv*4, tb8 = tb*8;
    const float* h2 = (const float*)g_h2;

    #pragma unroll
    for (int p=0;p<3;p++)
        load_tile(p, tid, h2 + p*1024, W + (size_t)p*16*VV, VV, v0, sW, sA);

    float4 bv = *(const float4*)(ob + v0 + vl);
    u64 b01 = pk(bv.x,bv.y), b23 = pk(bv.z,bv.w);
    u64 A00=b01,A01=b23,A10=b01,A11=b23,A20=b01,A21=b23,A30=b01,A31=b23;

    for (int u=0; u<64; u++){
        int rem = 63-u;
        if (rem >= 2) CP_WAIT(2);
        else if (rem == 1) CP_WAIT(1);
        else CP_WAIT(0);
        __syncthreads();
        if (u+3 < 64)
            load_tile((u+3)&3, tid, h2 + (u+3)*1024,
                      W + (size_t)(u+3)*16*VV, VV, v0, sW, sA);
        mma_tile(sW[u&3], sA[u&3], vl, tb8, A00,A01,A10,A11,A20,A21,A30,A31);
    }
    float2 r0a=up(A00), r0b=up(A01);
    float2 r1a=up(A10), r1b=up(A11);
    float2 r2a=up(A20), r2b=up(A21);
    float2 r3a=up(A30), r3b=up(A31);
    float rv[4][4] = {
        {r0a.x,r0a.y,r0b.x,r0b.y},
        {r1a.x,r1a.y,r1b.x,r1b.y},
        {r2a.x,r2a.y,r2b.x,r2b.y},
        {r3a.x,r3a.y,r3b.x,r3b.y}};
    #pragma unroll
    for (int i=0;i<4;i++)
        *(float4*)(out + ((size_t)(b0+i)*LL + t)*VV + v0+vl) =
            make_float4(rv[i][0],rv[i][1],rv[i][2],rv[i][3]);

    // fused argmax: warp covers full 128 cols for batches b0..b0+3
    #pragma unroll
    for (int i=0;i<4;i++){
        float mx = rv[i][0]; int mi = 0;
        #pragma unroll
        for (int j=1;j<4;j++) if (rv[i][j] > mx){ mx = rv[i][j]; mi = j; }
        u64 kp = ((u64)ordf(mx)<<32) | (unsigned)(~(unsigned)(v0+vl+mi));
        #pragma unroll
        for (int o=16;o>0;o>>=1){
            u64 q = __shfl_xor_sync(0xffffffffu, kp, o);
            if (q > kp) kp = q;
        }
        if (tv==0) atomicMax(&g_slot[b0+i], kp);
    }
}

// =====================================================================
// log_softmax normalize (2 passes; max from slot) + token extract
// =====================================================================
__global__ __launch_bounds__(512) void lsm_norm(float* __restrict__ out, int t)
{
    int b = blockIdx.x, tid = threadIdx.x;
    float* row = out + ((size_t)b*LL + t)*VV;
    u64 slot = g_slot[b];
    if (tid==0) g_tok[b] = (int)(~(unsigned)(slot & 0xFFFFFFFFu));
    float gm = unordf((unsigned)(slot>>32));
    __shared__ float sm[512];

    float s = 0.0f;
    for (int v=tid*4; v<VV; v+=2048){
        float4 xv = *(const float4*)(row+v);
        s += expf(xv.x-gm) + expf(xv.y-gm) + expf(xv.z-gm) + expf(xv.w-gm);
    }
    sm[tid]=s;
    __syncthreads();
    for (int st=256; st>0; st>>=1){
        if (tid < st) sm[tid] += sm[tid+st];
        __syncthreads();
    }
    float lse = gm + logf(sm[0]);
    for (int v=tid*4; v<VV; v+=2048){
        float4 xv = *(const float4*)(row+v);
        xv.x -= lse; xv.y -= lse; xv.z -= lse; xv.w -= lse;
        *(float4*)(row+v) = xv;
    }
}

// =====================================================================
extern "C" void kernel_launch(void* const* d_in, const int* in_sizes, int n_in,
                              void* d_out, int out_size)
{
    const int*   x    = (const int*)  d_in[0];
    const float* eemb = (const float*)d_in[1];
    const float* ewx  = (const float*)d_in[2];
    const float* ewh  = (const float*)d_in[3];
    const float* eb   = (const float*)d_in[4];
    const float* demb = (const float*)d_in[5];
    const float* aw   = (const float*)d_in[6];
    const float* ab   = (const float*)d_in[7];
    const float* cw   = (const float*)d_in[8];
    const float* cb   = (const float*)d_in[9];
    const float* dwx  = (const float*)d_in[10];
    const float* dwh  = (const float*)d_in[11];
    const float* db   = (const float*)d_in[12];
    const float* ow   = (const float*)d_in[13];
    const float* obb  = (const float*)d_in[14];
    float* out = (float*)d_out;

    float *p_xemb2, *p_h2, *p_inp2, *p_e2, *p_ctx2, *p_part, *p_part2;
    cudaGetSymbolAddress((void**)&p_xemb2, g_xemb2);
    cudaGetSymbolAddress((void**)&p_h2,    g_h2);
    cudaGetSymbolAddress((void**)&p_inp2,  g_inp2);
    cudaGetSymbolAddress((void**)&p_e2,    g_e2);
    cudaGetSymbolAddress((void**)&p_ctx2,  g_ctx2);
    cudaGetSymbolAddress((void**)&p_part,  g_part);
    cudaGetSymbolAddress((void**)&p_part2, g_part2);

    // ---- encoder ----
    init_state<<<128,256>>>(x, eemb, 0);
    for (int t=0;t<LL;t++){
        // K = 512 emb (32 units) + 1024 h (64 units) = 96 units; 4 slices x 24
        gemm_seg<<<dim3(32,4),256>>>(p_xemb2, ewx, 32, p_h2, ewh, G4, 24, p_part);
        lstm_update<<<32,256>>>(eb, 1, t, x, eemb);
    }

    // ---- decoder ----
    init_state<<<128,256>>>(x, eemb, 1);
    for (int t=0;t<LL;t++){
        attn_ctx<<<BB,256>>>(demb, aw, ab);
        // comb: K = 1024 e + 1024 ctx = 128 units; 16 slices x 8
        gemm_seg<<<dim3(8,16),256>>>(p_e2, cw, 64, p_ctx2, cw + (size_t)1024*HH, HH, 8, p_part2);
        comb_fin<<<32,256>>>(cb);
        // gates: K = 1024 inp + 1024 h = 128 units; 4 slices x 32
        gemm_seg<<<dim3(32,4),256>>>(p_inp2, dwx, 64, p_h2, dwh, G4, 32, p_part);
        lstm_update<<<32,256>>>(db, 0, t, x, eemb);
        out_proj<<<250,256>>>(ow, obb, out, t);
        lsm_norm<<<BB,512>>>(out, t);
    }
}

// round 8
// speedup vs baseline: 1.3808x; 1.3808x over previous
#include <cuda_runtime.h>
#include <math.h>
#include <cstdint>

#define BB 32
#define EE 512
#define HH 1024
#define G4 4096
#define LL 64
#define VV 32000

typedef unsigned long long u64;

// ---------------- device scratch ----------------
__device__ __align__(16) float g_h[BB*HH];
__device__ __align__(16) float g_c[BB*HH];
__device__ __align__(16) float g_enc[LL*BB*HH];     // [l][b][d]
__device__ __align__(16) float g_hT[HH*BB];         // [k][b]
__device__ __align__(16) float g_eT[HH*BB];
__device__ __align__(16) float g_ctxT[HH*BB];
__device__ __align__(16) float g_inpT[HH*BB];
__device__ __align__(16) float g_xembT[EE*BB];
__device__ __align__(16) float g_part[16*BB*G4];    // gate partials (8MB)
__device__ __align__(16) float g_part2[32*BB*HH];   // comb partials (4MB)
__device__ u64 g_slotArr[LL*BB];                    // per-step argmax slots

// ---------------- helpers ----------------
__device__ __forceinline__ void fma2(u64 &d, u64 a, u64 b){
    asm("fma.rn.f32x2 %0, %1, %2, %0;" : "+l"(d) : "l"(a), "l"(b));
}
__device__ __forceinline__ u64 pk(float x, float y){
    u64 r; asm("mov.b64 %0,{%1,%2};" : "=l"(r) : "f"(x), "f"(y)); return r;
}
__device__ __forceinline__ float2 up(u64 v){
    float2 r; asm("mov.b64 {%0,%1},%2;" : "=f"(r.x), "=f"(r.y) : "l"(v)); return r;
}
__device__ __forceinline__ float sigf(float x){ return 1.0f/(1.0f + expf(-x)); }

__device__ __forceinline__ unsigned ordf(float f){
    unsigned u = __float_as_uint(f);
    return (u & 0x80000000u) ? ~u : (u | 0x80000000u);
}
__device__ __forceinline__ float unordf(unsigned u){
    return __uint_as_float((u & 0x80000000u) ? (u ^ 0x80000000u) : ~u);
}

__device__ __forceinline__ void cpa16(void* s, const void* g){
    uint32_t sa = (uint32_t)__cvta_generic_to_shared(s);
    asm volatile("cp.async.cg.shared.global [%0], [%1], 16;" :: "r"(sa), "l"(g));
}
#define CP_COMMIT asm volatile("cp.async.commit_group;" ::: "memory")
#define CP_WAIT(n) asm volatile("cp.async.wait_group %0;" :: "n"(n) : "memory")

// smem partition (dynamic): W 4 stages x 16KB, A 4 stages x 2KB
#define SMEM_BYTES (4*16384 + 4*2048)
#define SW_STAGE(sm,buf) ((float*)((sm) + (size_t)(buf)*16384))
#define SA_STAGE(sm,buf) ((float*)((sm) + 65536 + (size_t)(buf)*2048))

// ---------------- init ----------------
__global__ __launch_bounds__(256) void init_state(
    const int* __restrict__ x, const float* __restrict__ emb, int phase)
{
    int i = blockIdx.x*256 + threadIdx.x;   // 32768 threads
    if (i < BB*HH){ g_h[i]=0.0f; g_c[i]=0.0f; g_hT[i]=0.0f; }
    if (i < LL*BB) g_slotArr[i] = 0ULL;
    if (phase==0 && i < EE*BB){
        int k=i>>5, b=i&31;
        g_xembT[i] = emb[(size_t)x[b*LL]*EE + k];
    }
}

// =====================================================================
// Core 16-kk MMA micro-tile: per thread 4 cols x 16 batches (batch-pairs)
// =====================================================================
__device__ __forceinline__ void mma16(const float* pw, const float* pa, u64 acc[4][8])
{
    #pragma unroll
    for (int kk=0;kk<16;kk++){
        float4 w = *(const float4*)(pw + kk*256);
        u64 wd[4] = { pk(w.x,w.x), pk(w.y,w.y), pk(w.z,w.z), pk(w.w,w.w) };
        float4 av[4];
        #pragma unroll
        for (int i=0;i<4;i++) av[i] = *(const float4*)(pa + kk*32 + i*4);
        const u64* ap = (const u64*)av;
        #pragma unroll
        for (int c=0;c<4;c++){
            u64 wc = wd[c];
            #pragma unroll
            for (int p=0;p<8;p++) fma2(acc[c][p], wc, ap[p]);
        }
    }
}

__device__ __forceinline__ void load_tile(
    char* sm, int buf, int tid, const float* At, const float* Wp, int ldw, int colbase)
{
    float* sW = SW_STAGE(sm,buf);
    float* sA = SA_STAGE(sm,buf);
    #pragma unroll
    for (int r=0;r<8;r++){
        int i = tid + r*128;              // 1024 vec4 slots: 16 rows x 64
        int row = i>>6, col = (i&63)*4;
        cpa16(&sW[row*256+col], Wp + (size_t)row*ldw + colbase + col);
    }
    cpa16(&sA[tid*4], At + tid*4);
    CP_COMMIT;
}

__device__ __forceinline__ void seg_resolve(
    int g, int k1u, const float* A1, const float* W1,
    const float* A2, const float* W2, int ldw,
    const float*& At, const float*& Wp)
{
    if (g < k1u){ At = A1 + g*512; Wp = W1 + (size_t)g*16*ldw; }
    else { int h = g-k1u; At = A2 + h*512; Wp = W2 + (size_t)h*16*ldw; }
}

// =====================================================================
// Split-K 2-segment GEMM. A: [k][32] plain floats. W: [K][ldw] row-major.
// Block: 128 threads = 4 warps (2 colHalf x 2 batchHalf); 256 cols x 32 b.
// grid (ldw/256, nslices). 4-stage cp.async ring, 16-row tiles.
// =====================================================================
__global__ __launch_bounds__(128) void gemm_seg(
    const float* __restrict__ A1, const float* __restrict__ W1, int k1u,
    const float* __restrict__ A2, const float* __restrict__ W2,
    int ldw, int tpu, float* __restrict__ parts)
{
    extern __shared__ char sm[];
    int tid = threadIdx.x;
    int w = tid>>5, l = tid&31;
    int ch = w&1, bh = w>>1;
    int colbase = blockIdx.x*256;
    int slice = blockIdx.y;
    int u0 = slice*tpu;
    int thw = ch*128 + l*4;       // W col offset in tile
    int bb0 = bh*16;

    #pragma unroll
    for (int p=0;p<3;p++){
        const float *At,*Wp;
        seg_resolve(u0+p, k1u, A1,W1,A2,W2,ldw, At,Wp);
        load_tile(sm, p, tid, At, Wp, ldw, colbase);
    }

    u64 acc[4][8];
    #pragma unroll
    for (int c=0;c<4;c++)
        #pragma unroll
        for (int p=0;p<8;p++) acc[c][p]=0ULL;

    for (int u=0; u<tpu; u++){
        int rem = tpu-1-u;
        if (rem >= 2) CP_WAIT(2);
        else if (rem == 1) CP_WAIT(1);
        else CP_WAIT(0);
        __syncthreads();
        if (u+3 < tpu){
            const float *At,*Wp;
            seg_resolve(u0+u+3, k1u, A1,W1,A2,W2,ldw, At,Wp);
            load_tile(sm, (u+3)&3, tid, At, Wp, ldw, colbase);
        }
        mma16(SW_STAGE(sm,u&3) + thw, SA_STAGE(sm,u&3) + bb0, acc);
    }

    float* pp = parts + ((size_t)slice*BB + bb0)*ldw + colbase + thw;
    #pragma unroll
    for (int p=0;p<8;p++){
        float2 u0v=up(acc[0][p]), u1v=up(acc[1][p]), u2v=up(acc[2][p]), u3v=up(acc[3][p]);
        *(float4*)(pp + (size_t)(2*p)*ldw)   = make_float4(u0v.x,u1v.x,u2v.x,u3v.x);
        *(float4*)(pp + (size_t)(2*p+1)*ldw) = make_float4(u0v.y,u1v.y,u2v.y,u3v.y);
    }
}

// =====================================================================
// Combine NS gate-partial slices + LSTM cell (i,f,g,o). 4 cells/thread.
// Enc: stores enc row + gathers next-step embedding. grid 32 x 256.
// =====================================================================
template<int NS>
__global__ __launch_bounds__(256) void lstm_update(
    const float* __restrict__ bias, int isEnc, int t,
    const int* __restrict__ x, const float* __restrict__ emb)
{
    int gtid = blockIdx.x*256 + threadIdx.x;     // 8192
    int b = gtid>>8, d = (gtid&255)*4;

    float4 gi = *(const float4*)&bias[d];
    float4 gf = *(const float4*)&bias[HH+d];
    float4 gg = *(const float4*)&bias[2*HH+d];
    float4 go = *(const float4*)&bias[3*HH+d];
    #pragma unroll
    for (int s=0;s<NS;s++){
        const float* p = g_part + (size_t)(s*BB+b)*G4;
        float4 a = *(const float4*)&p[d];
        float4 bq = *(const float4*)&p[HH+d];
        float4 cq = *(const float4*)&p[2*HH+d];
        float4 dq = *(const float4*)&p[3*HH+d];
        gi.x+=a.x; gi.y+=a.y; gi.z+=a.z; gi.w+=a.w;
        gf.x+=bq.x; gf.y+=bq.y; gf.z+=bq.z; gf.w+=bq.w;
        gg.x+=cq.x; gg.y+=cq.y; gg.z+=cq.z; gg.w+=cq.w;
        go.x+=dq.x; go.y+=dq.y; go.z+=dq.z; go.w+=dq.w;
    }
    float4 c4 = *(const float4*)&g_c[b*HH+d];
    float ci[4]={c4.x,c4.y,c4.z,c4.w};
    float gia[4]={gi.x,gi.y,gi.z,gi.w}, gfa[4]={gf.x,gf.y,gf.z,gf.w};
    float gga[4]={gg.x,gg.y,gg.z,gg.w}, goa[4]={go.x,go.y,go.z,go.w};
    float hv[4];
    #pragma unroll
    for (int i=0;i<4;i++){
        float c = sigf(gfa[i])*ci[i] + sigf(gia[i])*tanhf(gga[i]);
        hv[i] = sigf(goa[i])*tanhf(c);
        ci[i] = c;
    }
    *(float4*)&g_c[b*HH+d] = make_float4(ci[0],ci[1],ci[2],ci[3]);
    *(float4*)&g_h[b*HH+d] = make_float4(hv[0],hv[1],hv[2],hv[3]);
    #pragma unroll
    for (int i=0;i<4;i++) g_hT[(d+i)*BB+b] = hv[i];

    if (isEnc){
        *(float4*)&g_enc[((size_t)t*BB+b)*HH+d] = make_float4(hv[0],hv[1],hv[2],hv[3]);
        if (t+1 < LL){
            for (int i=gtid;i<EE*BB;i+=8192){
                int k=i>>5, bb=i&31;
                g_xembT[i] = emb[(size_t)x[bb*LL+t+1]*EE + k];
            }
        }
    }
}

// =====================================================================
// Attention: tok from prev-step slot; e=dec_embed[tok];
// softmax([e,h]@attn_w+b); ctx. Writes eT, ctxT.
// =====================================================================
__global__ __launch_bounds__(256) void attn_ctx(
    const float* __restrict__ demb, const float* __restrict__ aw,
    const float* __restrict__ ab, int t)
{
    int b = blockIdx.x, tid = threadIdx.x;
    __shared__ float sE[HH], sH2[HH], sPP[4][64], sS[64];
    int tok = 127;
    if (t > 0){
        u64 s = g_slotArr[(t-1)*BB + b];
        tok = (int)(~(unsigned)(s & 0xFFFFFFFFu));
    }
    for (int k=tid; k<HH; k+=256){
        float e = demb[(size_t)tok*HH + k];
        sE[k]=e; g_eT[k*BB+b]=e;
        sH2[k]=g_h[b*HH+k];
    }
    __syncthreads();

    {   // scores: 4-way K split over 512-row chunks of attn_w
        int l = tid & 63, q = tid >> 6;
        const float* src = (q<2) ? (sE + q*512) : (sH2 + (q-2)*512);
        const float* wb  = aw + (size_t)q*512*64;
        float a0=0.f,a1=0.f,a2=0.f,a3=0.f,a4=0.f,a5=0.f,a6=0.f,a7=0.f;
        #pragma unroll 2
        for (int k=0;k<512;k+=8){
            a0 += src[k+0]*wb[(k+0)*64 + l];
            a1 += src[k+1]*wb[(k+1)*64 + l];
            a2 += src[k+2]*wb[(k+2)*64 + l];
            a3 += src[k+3]*wb[(k+3)*64 + l];
            a4 += src[k+4]*wb[(k+4)*64 + l];
            a5 += src[k+5]*wb[(k+5)*64 + l];
            a6 += src[k+6]*wb[(k+6)*64 + l];
            a7 += src[k+7]*wb[(k+7)*64 + l];
        }
        sPP[q][l] = ((a0+a1)+(a2+a3))+((a4+a5)+(a6+a7));
    }
    __syncthreads();
    if (tid == 0){
        float sv[64]; float m = -INFINITY;
        for (int i=0;i<64;i++){
            float v = sPP[0][i]+sPP[1][i]+sPP[2][i]+sPP[3][i]+ab[i];
            sv[i]=v; m = fmaxf(m,v);
        }
        float sum = 0.0f;
        for (int i=0;i<64;i++){ float e = expf(sv[i]-m); sS[i]=e; sum += e; }
        float inv = 1.0f/sum;
        for (int i=0;i<64;i++) sS[i] *= inv;
    }
    __syncthreads();
    {   // ctx: 4 contiguous d per thread
        int d = tid*4;
        float ax=0.f, ay=0.f, az=0.f, awc=0.f;
        #pragma unroll 8
        for (int l=0;l<64;l++){
            float s = sS[l];
            float4 ev = *(const float4*)&g_enc[((size_t)l*BB + b)*HH + d];
            ax += s*ev.x; ay += s*ev.y; az += s*ev.z; awc += s*ev.w;
        }
        g_ctxT[(d+0)*BB+b]=ax; g_ctxT[(d+1)*BB+b]=ay;
        g_ctxT[(d+2)*BB+b]=az; g_ctxT[(d+3)*BB+b]=awc;
    }
}

// =====================================================================
// comb partial reduce (32 slices) + bias + relu -> inpT. grid 32 x 256.
// =====================================================================
__global__ __launch_bounds__(256) void comb_fin(const float* __restrict__ cb)
{
    int gtid = blockIdx.x*256 + threadIdx.x;  // 8192
    int b = gtid>>8, d = (gtid&255)*4;
    float4 v = *(const float4*)&cb[d];
    #pragma unroll
    for (int s=0;s<32;s++){
        float4 a = *(const float4*)&g_part2[(size_t)(s*BB+b)*HH + d];
        v.x+=a.x; v.y+=a.y; v.z+=a.z; v.w+=a.w;
    }
    g_inpT[(d+0)*BB+b]=fmaxf(v.x,0.f);
    g_inpT[(d+1)*BB+b]=fmaxf(v.y,0.f);
    g_inpT[(d+2)*BB+b]=fmaxf(v.z,0.f);
    g_inpT[(d+3)*BB+b]=fmaxf(v.w,0.f);
}

// =====================================================================
// Output projection + fused argmax into g_slotArr[t]. grid 125 x 128.
// 256 cols x 32 batches per block; 64 sequential 16-row tiles.
// =====================================================================
__global__ __launch_bounds__(128) void out_proj(
    const float* __restrict__ W, const float* __restrict__ ob,
    float* __restrict__ out, int t)
{
    extern __shared__ char sm[];
    int tid = threadIdx.x;
    int w = tid>>5, l = tid&31;
    int ch = w&1, bh = w>>1;
    int colbase = blockIdx.x*256;
    int thw = ch*128 + l*4;
    int bb0 = bh*16;
    int gcol = colbase + thw;

    #pragma unroll
    for (int p=0;p<3;p++)
        load_tile(sm, p, tid, g_hT + p*512, W + (size_t)p*16*VV, VV, colbase);

    float4 bv = *(const float4*)(ob + gcol);
    u64 acc[4][8];
    #pragma unroll
    for (int p=0;p<8;p++){
        acc[0][p]=pk(bv.x,bv.x); acc[1][p]=pk(bv.y,bv.y);
        acc[2][p]=pk(bv.z,bv.z); acc[3][p]=pk(bv.w,bv.w);
    }

    for (int u=0; u<64; u++){
        int rem = 63-u;
        if (rem >= 2) CP_WAIT(2);
        else if (rem == 1) CP_WAIT(1);
        else CP_WAIT(0);
        __syncthreads();
        if (u+3 < 64)
            load_tile(sm, (u+3)&3, tid, g_hT + (u+3)*512,
                      W + (size_t)(u+3)*16*VV, VV, colbase);
        mma16(SW_STAGE(sm,u&3) + thw, SA_STAGE(sm,u&3) + bb0, acc);
    }

    #pragma unroll
    for (int p=0;p<8;p++){
        float2 u0v=up(acc[0][p]), u1v=up(acc[1][p]), u2v=up(acc[2][p]), u3v=up(acc[3][p]);
        float r0[4]={u0v.x,u1v.x,u2v.x,u3v.x};
        float r1[4]={u0v.y,u1v.y,u2v.y,u3v.y};
        *(float4*)(out + ((size_t)(bb0+2*p)*LL + t)*VV + gcol)   = make_float4(r0[0],r0[1],r0[2],r0[3]);
        *(float4*)(out + ((size_t)(bb0+2*p+1)*LL + t)*VV + gcol) = make_float4(r1[0],r1[1],r1[2],r1[3]);
        #pragma unroll
        for (int rr=0;rr<2;rr++){
            const float* rv = rr ? r1 : r0;
            float mx = rv[0]; int mi = 0;
            #pragma unroll
            for (int j=1;j<4;j++) if (rv[j] > mx){ mx = rv[j]; mi = j; }
            u64 kp = ((u64)ordf(mx)<<32) | (unsigned)(~(unsigned)(gcol+mi));
            #pragma unroll
            for (int o=16;o>0;o>>=1){
                u64 q = __shfl_xor_sync(0xffffffffu, kp, o);
                if (q > kp) kp = q;
            }
            if (l==0) atomicMax(&g_slotArr[t*BB + bb0 + 2*p + rr], kp);
        }
    }
}

// =====================================================================
// Final: log_softmax normalize all 64 steps. grid (64 t, 32 b) x 256.
// =====================================================================
__global__ __launch_bounds__(256) void lsm_all(float* __restrict__ out)
{
    int t = blockIdx.x, b = blockIdx.y, tid = threadIdx.x;
    float* row = out + ((size_t)b*LL + t)*VV;
    u64 slot = g_slotArr[t*BB + b];
    float gm = unordf((unsigned)(slot>>32));
    __shared__ float smr[256];

    float s = 0.0f;
    for (int v=tid*4; v<VV; v+=1024){
        float4 xv = *(const float4*)(row+v);
        s += expf(xv.x-gm) + expf(xv.y-gm) + expf(xv.z-gm) + expf(xv.w-gm);
    }
    smr[tid]=s;
    __syncthreads();
    for (int st=128; st>0; st>>=1){
        if (tid < st) smr[tid] += smr[tid+st];
        __syncthreads();
    }
    float lse = gm + logf(smr[0]);
    for (int v=tid*4; v<VV; v+=1024){
        float4 xv = *(const float4*)(row+v);
        xv.x -= lse; xv.y -= lse; xv.z -= lse; xv.w -= lse;
        *(float4*)(row+v) = xv;
    }
}

// =====================================================================
extern "C" void kernel_launch(void* const* d_in, const int* in_sizes, int n_in,
                              void* d_out, int out_size)
{
    const int*   x    = (const int*)  d_in[0];
    const float* eemb = (const float*)d_in[1];
    const float* ewx  = (const float*)d_in[2];
    const float* ewh  = (const float*)d_in[3];
    const float* eb   = (const float*)d_in[4];
    const float* demb = (const float*)d_in[5];
    const float* aw   = (const float*)d_in[6];
    const float* ab   = (const float*)d_in[7];
    const float* cw   = (const float*)d_in[8];
    const float* cb   = (const float*)d_in[9];
    const float* dwx  = (const float*)d_in[10];
    const float* dwh  = (const float*)d_in[11];
    const float* db   = (const float*)d_in[12];
    const float* ow   = (const float*)d_in[13];
    const float* obb  = (const float*)d_in[14];
    float* out = (float*)d_out;

    // unconditional (no static guards — harness rule); cheap, capture-safe
    cudaFuncSetAttribute(gemm_seg, cudaFuncAttributeMaxDynamicSharedMemorySize, SMEM_BYTES);
    cudaFuncSetAttribute(out_proj, cudaFuncAttributeMaxDynamicSharedMemorySize, SMEM_BYTES);

    float *p_xembT, *p_hT, *p_inpT, *p_eT, *p_ctxT, *p_part, *p_part2;
    cudaGetSymbolAddress((void**)&p_xembT, g_xembT);
    cudaGetSymbolAddress((void**)&p_hT,    g_hT);
    cudaGetSymbolAddress((void**)&p_inpT,  g_inpT);
    cudaGetSymbolAddress((void**)&p_eT,    g_eT);
    cudaGetSymbolAddress((void**)&p_ctxT,  g_ctxT);
    cudaGetSymbolAddress((void**)&p_part,  g_part);
    cudaGetSymbolAddress((void**)&p_part2, g_part2);

    // ---- encoder: K = 512 emb (32 units) + 1024 h (64 units); 12 slices x 8 ----
    init_state<<<128,256>>>(x, eemb, 0);
    for (int t=0;t<LL;t++){
        gemm_seg<<<dim3(16,12),128,SMEM_BYTES>>>(p_xembT, ewx, 32, p_hT, ewh, G4, 8, p_part);
        lstm_update<12><<<32,256>>>(eb, 1, t, x, eemb);
    }

    // ---- decoder ----
    init_state<<<128,256>>>(x, eemb, 1);
    for (int t=0;t<LL;t++){
        attn_ctx<<<BB,256>>>(demb, aw, ab, t);
        // comb: 128 units; 32 slices x 4
        gemm_seg<<<dim3(4,32),128,SMEM_BYTES>>>(p_eT, cw, 64, p_ctxT, cw + (size_t)1024*HH, HH, 4, p_part2);
        comb_fin<<<32,256>>>(cb);
        // gates: 128 units; 16 slices x 8
        gemm_seg<<<dim3(16,16),128,SMEM_BYTES>>>(p_inpT, dwx, 64, p_hT, dwh, G4, 8, p_part);
        lstm_update<16><<<32,256>>>(db, 0, t, x, eemb);
        out_proj<<<125,128,SMEM_BYTES>>>(ow, obb, out, t);
    }
    lsm_all<<<dim3(LL,BB),256>>>(out);
}